// round 1
// baseline (speedup 1.0000x reference)
#include <cuda_runtime.h>
#include <cstdint>

// ---------------- Problem dims ----------------
#define B_DIM   64
#define T_DIM   500
#define IN_DIM  512
#define HID_DIM 2048
#define OUT_DIM 128
#define M_DIM   (B_DIM * T_DIM)          // 32000

// LIF constants (f64-accurate values rounded to f32, matching jnp weak-type promotion)
#define A_S1 0.81873075307798182f   // exp(-1/5)
#define SC1  0.90634623461009088f   // (1-A_S1)*5
#define A_M1 0.90483741803595952f   // exp(-1/10)
#define BM1  0.09516258196404048f   // 1-A_M1
#define TH1  0.5f
#define A_S2 0.90483741803595952f   // exp(-1/10)
#define SC2  0.95162581964040482f   // (1-A_S2)*10
#define A_M2 0.95122942450071402f   // exp(-1/20)
#define BM2  0.04877057549928598f   // 1-A_M2
#define TH2  1.0f

// ---------------- Scratch (device globals: allocation-free rule) ----------------
__device__ float g_c1[(size_t)M_DIM * HID_DIM];   // 262 MB: X @ W1
__device__ float g_c2[(size_t)M_DIM * OUT_DIM];   // 16.4 MB: spk1 @ W2

// ---------------- fp32 SGEMM: C[MxN] = A[MxK] @ B[KxN], all row-major ----------------
// BM=128, BN=128, BK=16, 256 threads, 8x8 per-thread microtile.
// All dims here divide the tile sizes exactly (M=32000, N in {2048,128}, K in {512,2048}).
#define GBM 128
#define GBN 128
#define GBK 16
#define GTM 8
#define GTN 8

__global__ __launch_bounds__(256, 2)
void sgemm_kernel(const float* __restrict__ A, const float* __restrict__ B,
                  float* __restrict__ C, int M, int N, int K) {
    __shared__ float As[GBK][GBM];   // transposed A tile
    __shared__ float Bs[GBK][GBN];

    const int tid  = threadIdx.x;
    const int brow = blockIdx.y * GBM;
    const int bcol = blockIdx.x * GBN;

    const int trow = (tid / (GBN / GTN)) * GTM;   // 0..120 step 8
    const int tcol = (tid % (GBN / GTN)) * GTN;   // 0..120 step 8

    float acc[GTM][GTN] = {};
    float ar[GTM], br[GTN];

    for (int k0 = 0; k0 < K; k0 += GBK) {
        // Load A tile: BM x BK = 2048 floats = 512 float4; 2 per thread.
        #pragma unroll
        for (int i = 0; i < 2; i++) {
            int s   = tid + i * 256;
            int row = s >> 2;              // 0..511 -> 0..127
            int kc  = (s & 3) << 2;        // 0,4,8,12
            float4 v = *reinterpret_cast<const float4*>(
                &A[(size_t)(brow + row) * K + k0 + kc]);
            As[kc + 0][row] = v.x;
            As[kc + 1][row] = v.y;
            As[kc + 2][row] = v.z;
            As[kc + 3][row] = v.w;
        }
        // Load B tile: BK x BN = 2048 floats = 512 float4; 2 per thread.
        #pragma unroll
        for (int i = 0; i < 2; i++) {
            int s   = tid + i * 256;
            int row = s >> 5;              // 0..15
            int c4  = (s & 31) << 2;       // 0..124
            *reinterpret_cast<float4*>(&Bs[row][c4]) =
                *reinterpret_cast<const float4*>(
                    &B[(size_t)(k0 + row) * N + bcol + c4]);
        }
        __syncthreads();

        #pragma unroll
        for (int k = 0; k < GBK; k++) {
            #pragma unroll
            for (int i = 0; i < GTM; i++) ar[i] = As[k][trow + i];
            #pragma unroll
            for (int j = 0; j < GTN; j++) br[j] = Bs[k][tcol + j];
            #pragma unroll
            for (int i = 0; i < GTM; i++)
                #pragma unroll
                for (int j = 0; j < GTN; j++)
                    acc[i][j] = fmaf(ar[i], br[j], acc[i][j]);
        }
        __syncthreads();
    }

    #pragma unroll
    for (int i = 0; i < GTM; i++)
        #pragma unroll
        for (int j = 0; j < GTN; j += 4) {
            float4 v = make_float4(acc[i][j], acc[i][j+1], acc[i][j+2], acc[i][j+3]);
            *reinterpret_cast<float4*>(
                &C[(size_t)(brow + trow + i) * N + bcol + tcol + j]) = v;
        }
}

// ---------------- Layer-1 LIF scan: per-(b,h) element, loop over T ----------------
__global__ __launch_bounds__(256)
void scan1_kernel(const float* __restrict__ c1,
                  float* __restrict__ spk1, float* __restrict__ mems1) {
    int idx = blockIdx.x * blockDim.x + threadIdx.x;   // 0..131071
    if (idx >= B_DIM * HID_DIM) return;
    int b = idx >> 11;           // / HID_DIM
    int h = idx & (HID_DIM - 1);

    size_t base = (size_t)b * T_DIM * HID_DIM + h;
    float syn = 0.f, mem = 0.f;
    for (int t = 0; t < T_DIM; t++) {
        size_t o = base + (size_t)t * HID_DIM;
        syn = A_S1 * syn + SC1 * c1[o];
        mem = A_M1 * mem + BM1 * syn;
        float s = (mem - TH1 > 0.f) ? 1.f : 0.f;
        mem -= s * TH1;
        spk1[o]  = s;
        mems1[o] = mem;
    }
}

// ---------------- Layer-2 LIF scan + time reduction ----------------
__global__ __launch_bounds__(256)
void scan2_kernel(const float* __restrict__ c2, float* __restrict__ out,
                  float* __restrict__ spk2, float* __restrict__ mems2) {
    int idx = blockIdx.x * blockDim.x + threadIdx.x;   // 0..8191
    if (idx >= B_DIM * OUT_DIM) return;
    int b = idx >> 7;            // / OUT_DIM
    int o = idx & (OUT_DIM - 1);

    size_t base = (size_t)b * T_DIM * OUT_DIM + o;
    float syn = 0.f, mem = 0.f, acc = 0.f;
    for (int t = 0; t < T_DIM; t++) {
        size_t off = base + (size_t)t * OUT_DIM;
        syn = A_S2 * syn + SC2 * c2[off];
        mem = A_M2 * mem + BM2 * syn;
        float s = (mem - TH2 > 0.f) ? 1.f : 0.f;
        mem -= s * TH2;
        spk2[off]  = s;
        mems2[off] = mem;
        if (t > 0) acc += mem;   // output = sum(mems2[1:]) / T
    }
    out[(size_t)b * OUT_DIM + o] = acc / (float)T_DIM;
}

// ---------------- Launch ----------------
extern "C" void kernel_launch(void* const* d_in, const int* in_sizes, int n_in,
                              void* d_out, int out_size) {
    const float* x  = (const float*)d_in[0];   // [B, T, IN]
    const float* w1 = (const float*)d_in[1];   // [IN, HID]
    const float* w2 = (const float*)d_in[2];   // [HID, OUT]

    float* out   = (float*)d_out;                                   // [B, OUT]
    float* spk1  = out  + (size_t)B_DIM * OUT_DIM;                  // [B, T, HID]
    float* mems1 = spk1 + (size_t)B_DIM * T_DIM * HID_DIM;          // [B, T, HID]
    float* spk2  = mems1 + (size_t)B_DIM * T_DIM * HID_DIM;         // [B, T, OUT]
    float* mems2 = spk2 + (size_t)B_DIM * T_DIM * OUT_DIM;          // [B, T, OUT]

    float* c1; cudaGetSymbolAddress((void**)&c1, g_c1);
    float* c2; cudaGetSymbolAddress((void**)&c2, g_c2);

    // Stage 1: C1 = X @ W1   (M=32000, N=2048, K=512)
    {
        dim3 grid(HID_DIM / GBN, M_DIM / GBM);   // 16 x 250
        sgemm_kernel<<<grid, 256>>>(x, w1, c1, M_DIM, HID_DIM, IN_DIM);
    }
    // Stage 2: layer-1 scan -> spk1, mems1
    {
        int n = B_DIM * HID_DIM;                 // 131072
        scan1_kernel<<<n / 256, 256>>>(c1, spk1, mems1);
    }
    // Stage 3: C2 = spk1 @ W2  (M=32000, N=128, K=2048)
    {
        dim3 grid(OUT_DIM / GBN, M_DIM / GBM);   // 1 x 250
        sgemm_kernel<<<grid, 256>>>(spk1, w2, c2, M_DIM, OUT_DIM, HID_DIM);
    }
    // Stage 4: layer-2 scan + output reduction
    {
        int n = B_DIM * OUT_DIM;                 // 8192
        scan2_kernel<<<n / 256, 256>>>(c2, out, spk2, mems2);
    }
}